// round 11
// baseline (speedup 1.0000x reference)
#include <cuda_runtime.h>

#define NLOC 1024
#define NNEI 64
#define NDIM 128
#define EDIM 64
#define ADIM 64
#define ASEL 20

typedef unsigned long long ull;

// ---------------- scratch (static device memory; no allocation) ----------------
__device__ float g_pself[NLOC * NDIM];        // silu(node @ W_self + b_self)
__device__ float g_pW0[NLOC * NDIM];          // node @ W0 + b_ne
__device__ float g_pW1[NLOC * NDIM];          // node @ W1
__device__ float g_pV0[NLOC * EDIM];          // node @ V0 + b_es
__device__ float g_pV1[NLOC * EDIM];          // node @ V1
__device__ float g_pA1[NLOC * EDIM];          // node @ A1 + b_ea1
__device__ float g_pB1[NLOC * ADIM];          // node @ B1 + b_as
__device__ float g_eproj[NLOC * ASEL * 4 * 64]; // [l][j][A2,A3,B2,B3][64]
__device__ float g_red[NLOC * ASEL * EDIM];   // reduced angle message
__device__ float g_symin[NLOC * 768];         // grrg concat input to W_sym
__device__ float g_nedge[NLOC * NDIM];        // n_edge

// ---------------- helpers ----------------
__device__ __forceinline__ float silu_f(float x) { return __fdividef(x, 1.0f + __expf(-x)); }

__device__ __forceinline__ ull pack2(float lo, float hi) {
    ull r;
    asm("mov.b64 %0, {%1, %2};" : "=l"(r) : "f"(lo), "f"(hi));
    return r;
}
__device__ __forceinline__ float sum2(ull v) {
    float lo, hi;
    asm("mov.b64 {%0, %1}, %2;" : "=f"(lo), "=f"(hi) : "l"(v));
    return lo + hi;
}
__device__ __forceinline__ void fma2(ull &acc, ull a, ull b) {
    asm("fma.rn.f32x2 %0, %1, %2, %0;" : "+l"(acc) : "l"(a), "l"(b));
}
// 128-bit shared load directly into two 64-bit register pairs (no repacking movs)
__device__ __forceinline__ void lds_2x64(ull &a, ull &b, unsigned saddr) {
    asm volatile("ld.shared.v2.u64 {%0, %1}, [%2];" : "=l"(a), "=l"(b) : "r"(saddr));
}
__device__ __forceinline__ unsigned saddr_of(const void* p) {
    return (unsigned)__cvta_generic_to_shared(p);
}
__device__ __forceinline__ void cp_async16(unsigned sdst, const void* gsrc) {
    asm volatile("cp.async.cg.shared.global [%0], [%1], 16;" :: "r"(sdst), "l"(gsrc));
}
__device__ __forceinline__ void cp_commit() { asm volatile("cp.async.commit_group;"); }
__device__ __forceinline__ void cp_wait0()  { asm volatile("cp.async.wait_group 0;"); }

// ---------------- kernel A: per-node projections (16 nodes / block, pass = blockIdx.y) ----------------
__global__ void __launch_bounds__(128) k_nodeproj(
        const float* __restrict__ node,
        const float* __restrict__ W_self, const float* __restrict__ b_self,
        const float* __restrict__ W_ne,   const float* __restrict__ b_ne,
        const float* __restrict__ W_es,   const float* __restrict__ b_es,
        const float* __restrict__ W_ea1,  const float* __restrict__ b_ea1,
        const float* __restrict__ W_as,   const float* __restrict__ b_as)
{
    const int t    = threadIdx.x;      // 0..127
    const int l0   = blockIdx.x * 16;
    const int pass = blockIdx.y;       // 0:W_self 1:W0 2:W1 3:V0/V1 4:A1/B1
    __shared__ __align__(16) float xs[16][NDIM];
    {
        const float4* src = (const float4*)(node + l0 * NDIM);
        float4* dst = (float4*)(&xs[0][0]);
        #pragma unroll
        for (int i = 0; i < 4; i++) dst[t + 128 * i] = src[t + 128 * i];
    }
    __syncthreads();

    float acc[16];
    #pragma unroll
    for (int m = 0; m < 16; m++) acc[m] = 0.f;

    if (pass < 3) {
        const float* W = (pass == 0) ? W_self : ((pass == 1) ? W_ne : (W_ne + NDIM * NDIM));
        for (int k = 0; k < NDIM; k += 4) {
            float w0 = W[(k + 0) * NDIM + t];
            float w1 = W[(k + 1) * NDIM + t];
            float w2 = W[(k + 2) * NDIM + t];
            float w3 = W[(k + 3) * NDIM + t];
            #pragma unroll
            for (int m = 0; m < 16; m++) {
                float4 x = *(const float4*)(&xs[m][k]);
                acc[m] = fmaf(x.x, w0, acc[m]);
                acc[m] = fmaf(x.y, w1, acc[m]);
                acc[m] = fmaf(x.z, w2, acc[m]);
                acc[m] = fmaf(x.w, w3, acc[m]);
            }
        }
        if (pass == 0) {
            float b = b_self[t];
            #pragma unroll
            for (int m = 0; m < 16; m++) g_pself[(l0 + m) * NDIM + t] = silu_f(acc[m] + b);
        } else if (pass == 1) {
            float b = b_ne[t];
            #pragma unroll
            for (int m = 0; m < 16; m++) g_pW0[(l0 + m) * NDIM + t] = acc[m] + b;
        } else {
            #pragma unroll
            for (int m = 0; m < 16; m++) g_pW1[(l0 + m) * NDIM + t] = acc[m];
        }
    } else {
        const int d = t & 63;
        const float* W;
        if (pass == 3) W = W_es + ((t < 64) ? 0 : NDIM * EDIM) + d;
        else           W = ((t < 64) ? W_ea1 : W_as) + 64 * 64 + d;
        for (int k = 0; k < NDIM; k += 4) {
            float w0 = W[(k + 0) * 64];
            float w1 = W[(k + 1) * 64];
            float w2 = W[(k + 2) * 64];
            float w3 = W[(k + 3) * 64];
            #pragma unroll
            for (int m = 0; m < 16; m++) {
                float4 x = *(const float4*)(&xs[m][k]);
                acc[m] = fmaf(x.x, w0, acc[m]);
                acc[m] = fmaf(x.y, w1, acc[m]);
                acc[m] = fmaf(x.z, w2, acc[m]);
                acc[m] = fmaf(x.w, w3, acc[m]);
            }
        }
        if (pass == 3) {
            if (t < 64) {
                float b = b_es[d];
                #pragma unroll
                for (int m = 0; m < 16; m++) g_pV0[(l0 + m) * EDIM + d] = acc[m] + b;
            } else {
                #pragma unroll
                for (int m = 0; m < 16; m++) g_pV1[(l0 + m) * EDIM + d] = acc[m];
            }
        } else {
            if (t < 64) {
                float b = b_ea1[d];
                #pragma unroll
                for (int m = 0; m < 16; m++) g_pA1[(l0 + m) * EDIM + d] = acc[m] + b;
            } else {
                float b = b_as[d];
                #pragma unroll
                for (int m = 0; m < 16; m++) g_pB1[(l0 + m) * ADIM + d] = acc[m] + b;
            }
        }
    }
}

// ---------------- kernel A2: e_ang projections (A2,A3,B2,B3); 1 node / block ----------------
__global__ void __launch_bounds__(256) k_eproj(const float* __restrict__ edge,
                                               const float* __restrict__ W_ea1,
                                               const float* __restrict__ W_as)
{
    const int t  = threadIdx.x;      // 0..255
    const int l  = blockIdx.x;
    const int which = t >> 6;        // 0:A2 1:A3 2:B2 3:B3
    const int d = t & 63;
    const float* Wsrc = ((which < 2) ? W_ea1 : W_as) + ((which & 1) ? 256 * 64 : 192 * 64) + d;
    ull w2[32];
    #pragma unroll
    for (int kk = 0; kk < 32; kk++)
        w2[kk] = pack2(Wsrc[(2 * kk) * 64], Wsrc[(2 * kk + 1) * 64]);

    __shared__ __align__(16) float rows[ASEL][64];   // 5 KB
    const unsigned rbase = saddr_of(&rows[0][0]);

    {
        const float4* src = (const float4*)(edge + (size_t)l * NNEI * EDIM);
        float4* dst = (float4*)(&rows[0][0]);
        for (int q = t; q < ASEL * 16; q += 256) dst[q] = src[q];
    }
    __syncthreads();
    for (int j = 0; j < ASEL; j += 2) {
        const unsigned a_j0 = rbase + j * 256;
        const unsigned a_j1 = a_j0 + 256;
        ull a0 = 0, a1 = 0, c0 = 0, c1 = 0;
        #pragma unroll
        for (int kk = 0; kk < 16; kk++) {
            ull x0, x1, y0, y1;
            lds_2x64(x0, x1, a_j0 + kk * 16);
            lds_2x64(y0, y1, a_j1 + kk * 16);
            fma2(a0, w2[2 * kk],     x0);
            fma2(a1, w2[2 * kk + 1], x1);
            fma2(c0, w2[2 * kk],     y0);
            fma2(c1, w2[2 * kk + 1], y1);
        }
        g_eproj[((l * ASEL + j)     * 4 + which) * 64 + d] = sum2(a0) + sum2(a1);
        g_eproj[((l * ASEL + j + 1) * 4 + which) * 64 + d] = sum2(c0) + sum2(c1);
    }
}

// ---------------- kernel B: edge path + grrg + n_edge (2 nodes / block, 384 thr) ----------------
__global__ void __launch_bounds__(384) k_edge(const float* __restrict__ node_ext,
                                              const float* __restrict__ edge,
                                              const float* __restrict__ h2,
                                              const float* __restrict__ sw,
                                              const int*   __restrict__ nlist,
                                              const float* __restrict__ W_ne,
                                              const float* __restrict__ W_es,
                                              const float* __restrict__ res_e,
                                              float* __restrict__ out_edge)
{
    const int t    = threadIdx.x;          // 0..383
    const int half = t / 192;              // node within block
    const int tt   = t - half * 192;       // 0..191
    const int l    = blockIdx.x * 2 + half;
    __shared__ __align__(16) float e_sm[2][NNEI][EDIM];  // 32 KB
    __shared__ float sw_sm[2][NNEI];
    __shared__ int   nl_sm[2][NNEI];
    __shared__ float h2_sm[2][NNEI][3];
    __shared__ float hg_sm[2][3 * NDIM + 3 * EDIM];

    {
        const float4* src = (const float4*)(edge + (size_t)l * NNEI * EDIM);
        float4* dst = (float4*)(&e_sm[half][0][0]);
        for (int i = tt; i < NNEI * EDIM / 4; i += 192) dst[i] = src[i];
        for (int i = tt; i < NNEI; i += 192) { sw_sm[half][i] = sw[l * NNEI + i]; nl_sm[half][i] = nlist[l * NNEI + i]; }
        for (int i = tt; i < NNEI * 3; i += 192) h2_sm[half][i / 3][i % 3] = h2[l * NNEI * 3 + i];
    }
    __syncthreads();

    const bool isA = (tt < NDIM);
    const int  d   = tt - NDIM;   // only meaningful for !isA
    ull w2[32];
    if (isA) {
        #pragma unroll
        for (int kk = 0; kk < 32; kk++)
            w2[kk] = pack2(W_ne[(256 + 2 * kk) * NDIM + tt], W_ne[(256 + 2 * kk + 1) * NDIM + tt]);
    } else {
        #pragma unroll
        for (int kk = 0; kk < 32; kk++)
            w2[kk] = pack2(W_es[(256 + 2 * kk) * EDIM + d], W_es[(256 + 2 * kk + 1) * EDIM + d]);
    }
    const float pv0 = isA ? g_pW0[l * NDIM + tt] : g_pV0[l * EDIM + d];
    const float rese0 = isA ? 0.f : res_e[d];
    const unsigned ebase = saddr_of(&e_sm[half][0][0]);

    float accNE = 0.f, hg0 = 0.f, hg1 = 0.f, hg2 = 0.f;

    for (int n = 0; n < NNEI; n += 2) {
        const int   idx0 = nl_sm[half][n],     idx1 = nl_sm[half][n + 1];
        const float sw0  = sw_sm[half][n],     sw1  = sw_sm[half][n + 1];
        // hoist random gathers so they overlap the fma chains
        float gproj0, gproj1, gnode0 = 0.f, gnode1 = 0.f;
        if (isA) {
            gproj0 = g_pW1[idx0 * NDIM + tt];
            gproj1 = g_pW1[idx1 * NDIM + tt];
            gnode0 = node_ext[idx0 * NDIM + tt];
            gnode1 = node_ext[idx1 * NDIM + tt];
        } else {
            gproj0 = g_pV1[idx0 * EDIM + d];
            gproj1 = g_pV1[idx1 * EDIM + d];
        }
        const unsigned a_n0 = ebase + n * 256;
        const unsigned a_n1 = a_n0 + 256;
        ull a0 = 0, a1 = 0, c0 = 0, c1 = 0;
        #pragma unroll
        for (int kk = 0; kk < 16; kk++) {
            ull x0, x1, y0, y1;
            lds_2x64(x0, x1, a_n0 + kk * 16);
            lds_2x64(y0, y1, a_n1 + kk * 16);
            fma2(a0, w2[2 * kk],     x0);
            fma2(a1, w2[2 * kk + 1], x1);
            fma2(c0, w2[2 * kk],     y0);
            fma2(c1, w2[2 * kk + 1], y1);
        }
        float s0 = sum2(a0) + sum2(a1) + pv0 + gproj0;
        float s1 = sum2(c0) + sum2(c1) + pv0 + gproj1;
        if (isA) {
            accNE = fmaf(silu_f(s0), sw0, accNE);
            accNE = fmaf(silu_f(s1), sw1, accNE);
            float gw0 = gnode0 * sw0;
            float gw1 = gnode1 * sw1;
            hg0 = fmaf(h2_sm[half][n][0], gw0, fmaf(h2_sm[half][n + 1][0], gw1, hg0));
            hg1 = fmaf(h2_sm[half][n][1], gw0, fmaf(h2_sm[half][n + 1][1], gw1, hg1));
            hg2 = fmaf(h2_sm[half][n][2], gw0, fmaf(h2_sm[half][n + 1][2], gw1, hg2));
        } else {
            float ev0 = e_sm[half][n][d], ev1 = e_sm[half][n + 1][d];
            out_edge[(l * NNEI + n)     * EDIM + d] = fmaf(rese0, silu_f(s0), ev0);
            out_edge[(l * NNEI + n + 1) * EDIM + d] = fmaf(rese0, silu_f(s1), ev1);
            float ge0 = ev0 * sw0, ge1 = ev1 * sw1;
            hg0 = fmaf(h2_sm[half][n][0], ge0, fmaf(h2_sm[half][n + 1][0], ge1, hg0));
            hg1 = fmaf(h2_sm[half][n][1], ge0, fmaf(h2_sm[half][n + 1][1], ge1, hg1));
            hg2 = fmaf(h2_sm[half][n][2], ge0, fmaf(h2_sm[half][n + 1][2], ge1, hg2));
        }
    }
    const float inv_nnei = 1.0f / NNEI;
    if (isA) {
        g_nedge[l * NDIM + tt] = accNE * inv_nnei;
        hg_sm[half][0 * NDIM + tt] = hg0 * inv_nnei;
        hg_sm[half][1 * NDIM + tt] = hg1 * inv_nnei;
        hg_sm[half][2 * NDIM + tt] = hg2 * inv_nnei;
    } else {
        hg_sm[half][3 * NDIM + 0 * EDIM + d] = hg0 * inv_nnei;
        hg_sm[half][3 * NDIM + 1 * EDIM + d] = hg1 * inv_nnei;
        hg_sm[half][3 * NDIM + 2 * EDIM + d] = hg2 * inv_nnei;
    }
    __syncthreads();

    // grrg outer products -> g_symin[l][768]   ([grrg(edge) 256 | grrg(nei) 512])
    const float third = 1.0f / 3.0f;
    #pragma unroll
    for (int g = 0; g < 4; g++) {
        int v = tt + g * 192;
        float o;
        if (v < 256) {
            int a = v >> 6, dd = v & 63;
            const float* he = hg_sm[half] + 3 * NDIM;
            o = (he[0 * EDIM + a] * he[0 * EDIM + dd] +
                 he[1 * EDIM + a] * he[1 * EDIM + dd] +
                 he[2 * EDIM + a] * he[2 * EDIM + dd]) * third;
        } else {
            int vv = v - 256;
            int a = vv >> 7, c = vv & 127;
            o = (hg_sm[half][0 * NDIM + a] * hg_sm[half][0 * NDIM + c] +
                 hg_sm[half][1 * NDIM + a] * hg_sm[half][1 * NDIM + c] +
                 hg_sm[half][2 * NDIM + a] * hg_sm[half][2 * NDIM + c]) * third;
        }
        g_symin[l * 768 + v] = o;
    }
}

// ---------------- kernel E: node_sym GEMM + finalize (4 nodes / block, split-k 4, 512 thr) ----------------
__global__ void __launch_bounds__(512) k_node_fin(const float* __restrict__ node,
                                                  const float* __restrict__ W_sym,
                                                  const float* __restrict__ b_sym,
                                                  const float* __restrict__ res_n,
                                                  float* __restrict__ out_node)
{
    const int t  = threadIdx.x;     // 0..511
    const int tt = t & 127;
    const int q  = t >> 7;          // k quarter 0..3
    const int l0 = blockIdx.x * 4;
    __shared__ __align__(16) float xs[4][768];   // 12 KB
    __shared__ float part[3][4][NDIM];           // 6 KB
    {
        const float4* src = (const float4*)(g_symin + (size_t)l0 * 768);
        float4* dst = (float4*)(&xs[0][0]);
        for (int i = t; i < 768; i += 512) dst[i] = src[i];
    }
    __syncthreads();

    float acc[4] = {0.f, 0.f, 0.f, 0.f};
    const int k0 = q * 192;
    #pragma unroll 2
    for (int k = k0; k < k0 + 192; k += 4) {
        float w0 = W_sym[(k + 0) * NDIM + tt];
        float w1 = W_sym[(k + 1) * NDIM + tt];
        float w2 = W_sym[(k + 2) * NDIM + tt];
        float w3 = W_sym[(k + 3) * NDIM + tt];
        #pragma unroll
        for (int m = 0; m < 4; m++) {
            float4 x = *(const float4*)(&xs[m][k]);
            acc[m] = fmaf(x.x, w0, acc[m]);
            acc[m] = fmaf(x.y, w1, acc[m]);
            acc[m] = fmaf(x.z, w2, acc[m]);
            acc[m] = fmaf(x.w, w3, acc[m]);
        }
    }
    if (q > 0) {
        #pragma unroll
        for (int m = 0; m < 4; m++) part[q - 1][m][tt] = acc[m];
    }
    __syncthreads();
    if (q == 0) {
        const float b  = b_sym[tt];
        const float r0 = res_n[tt], r1 = res_n[NDIM + tt], r2 = res_n[2 * NDIM + tt];
        #pragma unroll
        for (int m = 0; m < 4; m++) {
            const int l = l0 + m;
            float s = acc[m] + part[0][m][tt] + part[1][m][tt] + part[2][m][tt] + b;
            float ns = silu_f(s);
            out_node[l * NDIM + tt] = node[l * NDIM + tt]
                                    + r0 * g_pself[l * NDIM + tt]
                                    + r1 * ns
                                    + r2 * g_nedge[l * NDIM + tt];
        }
    }
}

// ---------------- kernel C: fused angle path, A+B per thread, cp.async pipeline ----------------
// 128 threads = two 64-thread groups; each group does 5 i's of the same node.
// 2 blocks per node. Warps 0..3 -> one per SMSP (balanced).
__global__ void __launch_bounds__(128) k_angle(const float* __restrict__ angle,
                                               const float* __restrict__ a_sw,
                                               const float* __restrict__ W_ea1,
                                               const float* __restrict__ W_as,
                                               const float* __restrict__ res_a,
                                               float* __restrict__ out_angle)
{
    const int t  = threadIdx.x;          // 0..127
    const int g  = t >> 6;               // i-group 0/1
    const int d  = t & 63;               // output channel, both paths
    const int l  = blockIdx.x >> 1;
    const int i0 = (blockIdx.x & 1) * 10 + g * 5;
    const int NI = 5;

    // both weight matrices resident: A0 (W_ea1 rows 0..63) and B0 (W_as rows 0..63)
    ull wA[32], wB[32];
    #pragma unroll
    for (int kk = 0; kk < 32; kk++) {
        wA[kk] = pack2(W_ea1[(2 * kk) * 64 + d], W_ea1[(2 * kk + 1) * 64 + d]);
        wB[kk] = pack2(W_as [(2 * kk) * 64 + d], W_as [(2 * kk + 1) * 64 + d]);
    }

    __shared__ __align__(16) float rows[2][2][ASEL][64]; // [group][buf] 20 KB
    __shared__ __align__(16) float a2s[ASEL][64];        // A2 adds (5 KB), shared by groups
    __shared__ __align__(16) float b2s[ASEL][64];        // B2 adds (5 KB), shared by groups
    __shared__ float asw_sm[ASEL];

    const float* eproj_l = g_eproj + (size_t)l * ASEL * 256;

    // kick off async copy of each group's first tile
    {
        const float* src = angle + (size_t)((l * ASEL + i0) * ASEL) * 64;
        unsigned sdst = saddr_of(&rows[g][0][0][0]);
        #pragma unroll
        for (int r = 0; r < 5; r++)
            cp_async16(sdst + (d + 64 * r) * 16, src + (d + 64 * r) * 4);
        cp_commit();
    }

    if (t < ASEL) asw_sm[t] = a_sw[l * ASEL + t];
    {
        float4* a4 = (float4*)(&a2s[0][0]);
        float4* b4 = (float4*)(&b2s[0][0]);
        for (int idx = t; idx < ASEL * 16; idx += 128) {
            int j = idx >> 4, q = idx & 15;
            a4[idx] = ((const float4*)(eproj_l + j * 256 +   0))[q];
            b4[idx] = ((const float4*)(eproj_l + j * 256 + 128))[q];
        }
    }
    const float cA1  = g_pA1[l * 64 + d];
    const float cB1  = g_pB1[l * 64 + d];
    const float resv = res_a[d];
    const float inv_sqrt_asel = 0.22360679774997896f;   // 1/sqrt(20)

    int buf = 0;
    for (int ii = 0; ii < NI; ii++) {
        const int i = i0 + ii;
        cp_wait0();          // this thread's slices of its group's tile landed
        __syncthreads();     // all slices visible; prev compute on buf^1 done (both groups)

        // prefetch tile ii+1 into the group's other buffer (hidden behind compute)
        if (ii + 1 < NI) {
            const float* src = angle + (size_t)((l * ASEL + i + 1) * ASEL) * 64;
            unsigned sdst = saddr_of(&rows[g][buf ^ 1][0][0]);
            #pragma unroll
            for (int r = 0; r < 5; r++)
                cp_async16(sdst + (d + 64 * r) * 16, src + (d + 64 * r) * 4);
            cp_commit();
        }

        const float baseA = cA1 + eproj_l[i * 256 +  64 + d];   // + A3[e_ang[l,i]]
        const float baseB = cB1 + eproj_l[i * 256 + 192 + d];   // + B3[e_ang[l,i]]
        float red = 0.f;
        const unsigned rb = saddr_of(&rows[g][buf][0][0]);
        #pragma unroll 2
        for (int j = 0; j < ASEL; j += 2) {
            const unsigned aj0 = rb + j * 256;
            const unsigned aj1 = aj0 + 256;
            ull A00 = 0, A01 = 0, B00 = 0, B01 = 0;
            ull A10 = 0, A11 = 0, B10 = 0, B11 = 0;
            #pragma unroll
            for (int kk = 0; kk < 16; kk++) {
                ull x0, x1, y0, y1;
                lds_2x64(x0, x1, aj0 + kk * 16);
                lds_2x64(y0, y1, aj1 + kk * 16);
                fma2(A00, wA[2 * kk],     x0);
                fma2(A01, wA[2 * kk + 1], x1);
                fma2(B00, wB[2 * kk],     x0);
                fma2(B01, wB[2 * kk + 1], x1);
                fma2(A10, wA[2 * kk],     y0);
                fma2(A11, wA[2 * kk + 1], y1);
                fma2(B10, wB[2 * kk],     y0);
                fma2(B11, wB[2 * kk + 1], y1);
            }
            const float vA0 = silu_f(sum2(A00) + sum2(A01) + baseA + a2s[j][d]);
            const float vB0 = silu_f(sum2(B00) + sum2(B01) + baseB + b2s[j][d]);
            const float vA1 = silu_f(sum2(A10) + sum2(A11) + baseA + a2s[j + 1][d]);
            const float vB1 = silu_f(sum2(B10) + sum2(B11) + baseB + b2s[j + 1][d]);
            red = fmaf(asw_sm[j],     vA0, red);
            red = fmaf(asw_sm[j + 1], vA1, red);
            const size_t o = (size_t)((l * ASEL + i) * ASEL + j) * 64 + d;
            out_angle[o]      = fmaf(resv, vB0, rows[g][buf][j][d]);
            out_angle[o + 64] = fmaf(resv, vB1, rows[g][buf][j + 1][d]);
        }
        g_red[(l * ASEL + i) * 64 + d] = red * asw_sm[i] * inv_sqrt_asel;
        buf ^= 1;
    }
}

// ---------------- kernel D: e_angle_msg GEMM + edge finalize (2 nodes / block) ----------------
__global__ void __launch_bounds__(128) k_eamsg(const float* __restrict__ W_ea2,
                                               const float* __restrict__ b_ea2,
                                               const float* __restrict__ res_e,
                                               float* __restrict__ out_edge)
{
    const int t = threadIdx.x;   // 0..127
    const int d = t & 63;
    const int l = blockIdx.x * 2 + (t >> 6);
    ull w2[32];
    #pragma unroll
    for (int kk = 0; kk < 32; kk++)
        w2[kk] = pack2(W_ea2[(2 * kk) * 64 + d], W_ea2[(2 * kk + 1) * 64 + d]);
    const float b   = b_ea2[d];
    const float re1 = res_e[64 + d];

    __shared__ __align__(16) float xs[2][ASEL][64];   // 10 KB
    {
        const float4* src = (const float4*)(g_red + (size_t)(blockIdx.x * 2) * ASEL * 64);
        float4* dst = (float4*)(&xs[0][0][0]);
        for (int q = t; q < 2 * ASEL * 16; q += 128) dst[q] = src[q];
    }
    __syncthreads();

    const unsigned xbase = saddr_of(&xs[t >> 6][0][0]);
    const float ypad = re1 * silu_f(b);   // padded rows contribute silu(b)
    for (int i = 0; i < NNEI; i++) {
        float add;
        if (i < ASEL) {
            const unsigned a_i = xbase + i * 256;
            ull a0 = 0, a1 = 0;
            #pragma unroll
            for (int kk = 0; kk < 16; kk++) {
                ull x0, x1;
                lds_2x64(x0, x1, a_i + kk * 16);
                fma2(a0, w2[2 * kk],     x0);
                fma2(a1, w2[2 * kk + 1], x1);
            }
            add = re1 * silu_f(sum2(a0) + sum2(a1) + b);
        } else {
            add = ypad;
        }
        const size_t o = (size_t)(l * NNEI + i) * 64 + d;
        out_edge[o] += add;
    }
}

// ---------------- stream/event resources (created once, at load time) ----------------
struct HxStreams {
    cudaStream_t s1 = nullptr;
    cudaEvent_t  evNP = nullptr, evEdge = nullptr, evJoin = nullptr;
    bool ok = false;
    HxStreams() {
        ok = (cudaStreamCreateWithFlags(&s1, cudaStreamNonBlocking) == cudaSuccess) &&
             (cudaEventCreateWithFlags(&evNP,   cudaEventDisableTiming) == cudaSuccess) &&
             (cudaEventCreateWithFlags(&evEdge, cudaEventDisableTiming) == cudaSuccess) &&
             (cudaEventCreateWithFlags(&evJoin, cudaEventDisableTiming) == cudaSuccess);
    }
};
static HxStreams g_hx;

// ---------------- launch ----------------
extern "C" void kernel_launch(void* const* d_in, const int* in_sizes, int n_in,
                              void* d_out, int out_size)
{
    (void)in_sizes; (void)n_in; (void)out_size;
    const float* node_ext = (const float*)d_in[0];
    const float* edge     = (const float*)d_in[1];
    const float* h2       = (const float*)d_in[2];
    const float* angle    = (const float*)d_in[3];
    const float* sw       = (const float*)d_in[4];
    const float* a_sw     = (const float*)d_in[5];
    const float* W_self   = (const float*)d_in[6];
    const float* b_self   = (const float*)d_in[7];
    const float* W_sym    = (const float*)d_in[8];
    const float* b_sym    = (const float*)d_in[9];
    const float* W_ne     = (const float*)d_in[10];
    const float* b_ne     = (const float*)d_in[11];
    const float* W_es     = (const float*)d_in[12];
    const float* b_es     = (const float*)d_in[13];
    const float* W_ea1    = (const float*)d_in[14];
    const float* b_ea1    = (const float*)d_in[15];
    const float* W_ea2    = (const float*)d_in[16];
    const float* b_ea2    = (const float*)d_in[17];
    const float* W_as     = (const float*)d_in[18];
    const float* b_as     = (const float*)d_in[19];
    const float* res_n    = (const float*)d_in[20];
    const float* res_e    = (const float*)d_in[21];
    const float* res_a    = (const float*)d_in[22];
    const int*   nlist    = (const int*)d_in[23];
    // d_in[24], d_in[25]: nlist_mask / a_nlist_mask — all True in this problem's setup

    float* out_node  = (float*)d_out;
    float* out_edge  = out_node + NLOC * NDIM;
    float* out_angle = out_edge + NLOC * NNEI * EDIM;

    if (g_hx.ok) {
        cudaStream_t s0 = 0, s1 = g_hx.s1;
        // chain 0: nodeproj -> edge -> node_fin
        k_nodeproj<<<dim3(NLOC / 16, 5), 128, 0, s0>>>(node_ext, W_self, b_self, W_ne, b_ne,
                                                       W_es, b_es, W_ea1, b_ea1, W_as, b_as);
        cudaEventRecord(g_hx.evNP, s0);
        // chain 1: eproj (independent), then angle after nodeproj
        k_eproj<<<NLOC, 256, 0, s1>>>(edge, W_ea1, W_as);
        cudaStreamWaitEvent(s1, g_hx.evNP, 0);
        k_edge<<<NLOC / 2, 384, 0, s0>>>(node_ext, edge, h2, sw, nlist, W_ne, W_es, res_e, out_edge);
        cudaEventRecord(g_hx.evEdge, s0);
        k_angle<<<NLOC * 2, 128, 0, s1>>>(angle, a_sw, W_ea1, W_as, res_a, out_angle);
        k_node_fin<<<NLOC / 4, 512, 0, s0>>>(node_ext, W_sym, b_sym, res_n, out_node);
        cudaStreamWaitEvent(s1, g_hx.evEdge, 0);
        k_eamsg<<<NLOC / 2, 128, 0, s1>>>(W_ea2, b_ea2, res_e, out_edge);
        cudaEventRecord(g_hx.evJoin, s1);
        cudaStreamWaitEvent(s0, g_hx.evJoin, 0);
    } else {
        // serial fallback (correct, no overlap)
        k_nodeproj<<<dim3(NLOC / 16, 5), 128>>>(node_ext, W_self, b_self, W_ne, b_ne,
                                                W_es, b_es, W_ea1, b_ea1, W_as, b_as);
        k_eproj<<<NLOC, 256>>>(edge, W_ea1, W_as);
        k_edge<<<NLOC / 2, 384>>>(node_ext, edge, h2, sw, nlist, W_ne, W_es, res_e, out_edge);
        k_node_fin<<<NLOC / 4, 512>>>(node_ext, W_sym, b_sym, res_n, out_node);
        k_angle<<<NLOC * 2, 128>>>(angle, a_sw, W_ea1, W_as, res_a, out_angle);
        k_eamsg<<<NLOC / 2, 128>>>(W_ea2, b_ea2, res_e, out_edge);
    }
}

// round 12
// speedup vs baseline: 1.0762x; 1.0762x over previous
#include <cuda_runtime.h>

#define NLOC 1024
#define NNEI 64
#define NDIM 128
#define EDIM 64
#define ADIM 64
#define ASEL 20

typedef unsigned long long ull;

// ---------------- scratch (static device memory; no allocation) ----------------
__device__ float g_pself[NLOC * NDIM];        // silu(node @ W_self + b_self)
__device__ float g_pW0[NLOC * NDIM];          // node @ W0 + b_ne
__device__ float g_pW1[NLOC * NDIM];          // node @ W1
__device__ float g_pV0[NLOC * EDIM];          // node @ V0 + b_es
__device__ float g_pV1[NLOC * EDIM];          // node @ V1
__device__ float g_pA1[NLOC * EDIM];          // node @ A1 + b_ea1
__device__ float g_pB1[NLOC * ADIM];          // node @ B1 + b_as
__device__ float g_eproj[NLOC * ASEL * 4 * 64]; // [l][j][A2,A3,B2,B3][64]
__device__ float g_red[NLOC * ASEL * EDIM];   // reduced angle message
__device__ float g_symin[NLOC * 768];         // grrg concat input to W_sym
__device__ float g_nedge[NLOC * NDIM];        // n_edge

// ---------------- helpers ----------------
__device__ __forceinline__ float silu_f(float x) { return __fdividef(x, 1.0f + __expf(-x)); }

__device__ __forceinline__ ull pack2(float lo, float hi) {
    ull r;
    asm("mov.b64 %0, {%1, %2};" : "=l"(r) : "f"(lo), "f"(hi));
    return r;
}
__device__ __forceinline__ float sum2(ull v) {
    float lo, hi;
    asm("mov.b64 {%0, %1}, %2;" : "=f"(lo), "=f"(hi) : "l"(v));
    return lo + hi;
}
__device__ __forceinline__ void fma2(ull &acc, ull a, ull b) {
    asm("fma.rn.f32x2 %0, %1, %2, %0;" : "+l"(acc) : "l"(a), "l"(b));
}
// 128-bit shared load directly into two 64-bit register pairs (no repacking movs)
__device__ __forceinline__ void lds_2x64(ull &a, ull &b, unsigned saddr) {
    asm volatile("ld.shared.v2.u64 {%0, %1}, [%2];" : "=l"(a), "=l"(b) : "r"(saddr));
}
__device__ __forceinline__ unsigned saddr_of(const void* p) {
    return (unsigned)__cvta_generic_to_shared(p);
}
__device__ __forceinline__ void cp_async16(unsigned sdst, const void* gsrc) {
    asm volatile("cp.async.cg.shared.global [%0], [%1], 16;" :: "r"(sdst), "l"(gsrc));
}
__device__ __forceinline__ void cp_commit() { asm volatile("cp.async.commit_group;"); }
__device__ __forceinline__ void cp_wait0()  { asm volatile("cp.async.wait_group 0;"); }

// ---------------- kernel A: per-node projections (16 nodes / block, pass = blockIdx.y) ----------------
__global__ void __launch_bounds__(128) k_nodeproj(
        const float* __restrict__ node,
        const float* __restrict__ W_self, const float* __restrict__ b_self,
        const float* __restrict__ W_ne,   const float* __restrict__ b_ne,
        const float* __restrict__ W_es,   const float* __restrict__ b_es,
        const float* __restrict__ W_ea1,  const float* __restrict__ b_ea1,
        const float* __restrict__ W_as,   const float* __restrict__ b_as)
{
    const int t    = threadIdx.x;      // 0..127
    const int l0   = blockIdx.x * 16;
    const int pass = blockIdx.y;       // 0:W_self 1:W0 2:W1 3:V0/V1 4:A1/B1
    __shared__ __align__(16) float xs[16][NDIM];
    {
        const float4* src = (const float4*)(node + l0 * NDIM);
        float4* dst = (float4*)(&xs[0][0]);
        #pragma unroll
        for (int i = 0; i < 4; i++) dst[t + 128 * i] = src[t + 128 * i];
    }
    __syncthreads();

    float acc[16];
    #pragma unroll
    for (int m = 0; m < 16; m++) acc[m] = 0.f;

    if (pass < 3) {
        const float* W = (pass == 0) ? W_self : ((pass == 1) ? W_ne : (W_ne + NDIM * NDIM));
        for (int k = 0; k < NDIM; k += 4) {
            float w0 = W[(k + 0) * NDIM + t];
            float w1 = W[(k + 1) * NDIM + t];
            float w2 = W[(k + 2) * NDIM + t];
            float w3 = W[(k + 3) * NDIM + t];
            #pragma unroll
            for (int m = 0; m < 16; m++) {
                float4 x = *(const float4*)(&xs[m][k]);
                acc[m] = fmaf(x.x, w0, acc[m]);
                acc[m] = fmaf(x.y, w1, acc[m]);
                acc[m] = fmaf(x.z, w2, acc[m]);
                acc[m] = fmaf(x.w, w3, acc[m]);
            }
        }
        if (pass == 0) {
            float b = b_self[t];
            #pragma unroll
            for (int m = 0; m < 16; m++) g_pself[(l0 + m) * NDIM + t] = silu_f(acc[m] + b);
        } else if (pass == 1) {
            float b = b_ne[t];
            #pragma unroll
            for (int m = 0; m < 16; m++) g_pW0[(l0 + m) * NDIM + t] = acc[m] + b;
        } else {
            #pragma unroll
            for (int m = 0; m < 16; m++) g_pW1[(l0 + m) * NDIM + t] = acc[m];
        }
    } else {
        const int d = t & 63;
        const float* W;
        if (pass == 3) W = W_es + ((t < 64) ? 0 : NDIM * EDIM) + d;
        else           W = ((t < 64) ? W_ea1 : W_as) + 64 * 64 + d;
        for (int k = 0; k < NDIM; k += 4) {
            float w0 = W[(k + 0) * 64];
            float w1 = W[(k + 1) * 64];
            float w2 = W[(k + 2) * 64];
            float w3 = W[(k + 3) * 64];
            #pragma unroll
            for (int m = 0; m < 16; m++) {
                float4 x = *(const float4*)(&xs[m][k]);
                acc[m] = fmaf(x.x, w0, acc[m]);
                acc[m] = fmaf(x.y, w1, acc[m]);
                acc[m] = fmaf(x.z, w2, acc[m]);
                acc[m] = fmaf(x.w, w3, acc[m]);
            }
        }
        if (pass == 3) {
            if (t < 64) {
                float b = b_es[d];
                #pragma unroll
                for (int m = 0; m < 16; m++) g_pV0[(l0 + m) * EDIM + d] = acc[m] + b;
            } else {
                #pragma unroll
                for (int m = 0; m < 16; m++) g_pV1[(l0 + m) * EDIM + d] = acc[m];
            }
        } else {
            if (t < 64) {
                float b = b_ea1[d];
                #pragma unroll
                for (int m = 0; m < 16; m++) g_pA1[(l0 + m) * EDIM + d] = acc[m] + b;
            } else {
                float b = b_as[d];
                #pragma unroll
                for (int m = 0; m < 16; m++) g_pB1[(l0 + m) * ADIM + d] = acc[m] + b;
            }
        }
    }
}

// ---------------- kernel A2: e_ang projections (A2,A3,B2,B3); 1 node / block ----------------
__global__ void __launch_bounds__(256) k_eproj(const float* __restrict__ edge,
                                               const float* __restrict__ W_ea1,
                                               const float* __restrict__ W_as)
{
    const int t  = threadIdx.x;      // 0..255
    const int l  = blockIdx.x;
    const int which = t >> 6;        // 0:A2 1:A3 2:B2 3:B3
    const int d = t & 63;
    const float* Wsrc = ((which < 2) ? W_ea1 : W_as) + ((which & 1) ? 256 * 64 : 192 * 64) + d;
    ull w2[32];
    #pragma unroll
    for (int kk = 0; kk < 32; kk++)
        w2[kk] = pack2(Wsrc[(2 * kk) * 64], Wsrc[(2 * kk + 1) * 64]);

    __shared__ __align__(16) float rows[ASEL][64];   // 5 KB
    const unsigned rbase = saddr_of(&rows[0][0]);

    {
        const float4* src = (const float4*)(edge + (size_t)l * NNEI * EDIM);
        float4* dst = (float4*)(&rows[0][0]);
        for (int q = t; q < ASEL * 16; q += 256) dst[q] = src[q];
    }
    __syncthreads();
    for (int j = 0; j < ASEL; j += 2) {
        const unsigned a_j0 = rbase + j * 256;
        const unsigned a_j1 = a_j0 + 256;
        ull a0 = 0, a1 = 0, c0 = 0, c1 = 0;
        #pragma unroll
        for (int kk = 0; kk < 16; kk++) {
            ull x0, x1, y0, y1;
            lds_2x64(x0, x1, a_j0 + kk * 16);
            lds_2x64(y0, y1, a_j1 + kk * 16);
            fma2(a0, w2[2 * kk],     x0);
            fma2(a1, w2[2 * kk + 1], x1);
            fma2(c0, w2[2 * kk],     y0);
            fma2(c1, w2[2 * kk + 1], y1);
        }
        g_eproj[((l * ASEL + j)     * 4 + which) * 64 + d] = sum2(a0) + sum2(a1);
        g_eproj[((l * ASEL + j + 1) * 4 + which) * 64 + d] = sum2(c0) + sum2(c1);
    }
}

// ---------------- kernel B: edge path + grrg + n_edge (block per node l, 192 thr) ----------------
__global__ void __launch_bounds__(192) k_edge(const float* __restrict__ node_ext,
                                              const float* __restrict__ edge,
                                              const float* __restrict__ h2,
                                              const float* __restrict__ sw,
                                              const int*   __restrict__ nlist,
                                              const float* __restrict__ W_ne,
                                              const float* __restrict__ W_es,
                                              const float* __restrict__ res_e,
                                              float* __restrict__ out_edge)
{
    const int t = threadIdx.x;   // 0..191
    const int l = blockIdx.x;
    __shared__ __align__(16) float e_sm[NNEI][EDIM];  // 16 KB
    __shared__ float sw_sm[NNEI];
    __shared__ int   nl_sm[NNEI];
    __shared__ float h2_sm[NNEI][3];
    __shared__ float hg_sm[3 * NDIM + 3 * EDIM];

    {
        const float4* src = (const float4*)(edge + (size_t)l * NNEI * EDIM);
        float4* dst = (float4*)(&e_sm[0][0]);
        for (int i = t; i < NNEI * EDIM / 4; i += 192) dst[i] = src[i];
        for (int i = t; i < NNEI; i += 192) { sw_sm[i] = sw[l * NNEI + i]; nl_sm[i] = nlist[l * NNEI + i]; }
        for (int i = t; i < NNEI * 3; i += 192) h2_sm[i / 3][i % 3] = h2[l * NNEI * 3 + i];
    }
    __syncthreads();

    const bool isA = (t < NDIM);
    const int  d   = t - NDIM;   // only meaningful for !isA
    ull w2[32];
    if (isA) {
        #pragma unroll
        for (int kk = 0; kk < 32; kk++)
            w2[kk] = pack2(W_ne[(256 + 2 * kk) * NDIM + t], W_ne[(256 + 2 * kk + 1) * NDIM + t]);
    } else {
        #pragma unroll
        for (int kk = 0; kk < 32; kk++)
            w2[kk] = pack2(W_es[(256 + 2 * kk) * EDIM + d], W_es[(256 + 2 * kk + 1) * EDIM + d]);
    }
    const float pv0 = isA ? g_pW0[l * NDIM + t] : g_pV0[l * EDIM + d];
    const float rese0 = isA ? 0.f : res_e[d];
    const unsigned ebase = saddr_of(&e_sm[0][0]);

    float accNE = 0.f, hg0 = 0.f, hg1 = 0.f, hg2 = 0.f;

    for (int n = 0; n < NNEI; n += 2) {
        const int   idx0 = nl_sm[n],     idx1 = nl_sm[n + 1];
        const float sw0  = sw_sm[n],     sw1  = sw_sm[n + 1];
        // hoist random gathers so they overlap the fma chains
        float gproj0, gproj1, gnode0 = 0.f, gnode1 = 0.f;
        if (isA) {
            gproj0 = g_pW1[idx0 * NDIM + t];
            gproj1 = g_pW1[idx1 * NDIM + t];
            gnode0 = node_ext[idx0 * NDIM + t];
            gnode1 = node_ext[idx1 * NDIM + t];
        } else {
            gproj0 = g_pV1[idx0 * EDIM + d];
            gproj1 = g_pV1[idx1 * EDIM + d];
        }
        const unsigned a_n0 = ebase + n * 256;
        const unsigned a_n1 = a_n0 + 256;
        ull a0 = 0, a1 = 0, c0 = 0, c1 = 0;
        #pragma unroll
        for (int kk = 0; kk < 16; kk++) {
            ull x0, x1, y0, y1;
            lds_2x64(x0, x1, a_n0 + kk * 16);
            lds_2x64(y0, y1, a_n1 + kk * 16);
            fma2(a0, w2[2 * kk],     x0);
            fma2(a1, w2[2 * kk + 1], x1);
            fma2(c0, w2[2 * kk],     y0);
            fma2(c1, w2[2 * kk + 1], y1);
        }
        float s0 = sum2(a0) + sum2(a1) + pv0 + gproj0;
        float s1 = sum2(c0) + sum2(c1) + pv0 + gproj1;
        if (isA) {
            accNE = fmaf(silu_f(s0), sw0, accNE);
            accNE = fmaf(silu_f(s1), sw1, accNE);
            float gw0 = gnode0 * sw0;
            float gw1 = gnode1 * sw1;
            hg0 = fmaf(h2_sm[n][0], gw0, fmaf(h2_sm[n + 1][0], gw1, hg0));
            hg1 = fmaf(h2_sm[n][1], gw0, fmaf(h2_sm[n + 1][1], gw1, hg1));
            hg2 = fmaf(h2_sm[n][2], gw0, fmaf(h2_sm[n + 1][2], gw1, hg2));
        } else {
            float ev0 = e_sm[n][d], ev1 = e_sm[n + 1][d];
            out_edge[(l * NNEI + n)     * EDIM + d] = fmaf(rese0, silu_f(s0), ev0);
            out_edge[(l * NNEI + n + 1) * EDIM + d] = fmaf(rese0, silu_f(s1), ev1);
            float ge0 = ev0 * sw0, ge1 = ev1 * sw1;
            hg0 = fmaf(h2_sm[n][0], ge0, fmaf(h2_sm[n + 1][0], ge1, hg0));
            hg1 = fmaf(h2_sm[n][1], ge0, fmaf(h2_sm[n + 1][1], ge1, hg1));
            hg2 = fmaf(h2_sm[n][2], ge0, fmaf(h2_sm[n + 1][2], ge1, hg2));
        }
    }
    const float inv_nnei = 1.0f / NNEI;
    if (isA) {
        g_nedge[l * NDIM + t] = accNE * inv_nnei;
        hg_sm[0 * NDIM + t] = hg0 * inv_nnei;
        hg_sm[1 * NDIM + t] = hg1 * inv_nnei;
        hg_sm[2 * NDIM + t] = hg2 * inv_nnei;
    } else {
        hg_sm[3 * NDIM + 0 * EDIM + d] = hg0 * inv_nnei;
        hg_sm[3 * NDIM + 1 * EDIM + d] = hg1 * inv_nnei;
        hg_sm[3 * NDIM + 2 * EDIM + d] = hg2 * inv_nnei;
    }
    __syncthreads();

    // grrg outer products -> g_symin[l][768]   ([grrg(edge) 256 | grrg(nei) 512])
    const float third = 1.0f / 3.0f;
    #pragma unroll
    for (int g = 0; g < 4; g++) {
        int v = t + g * 192;
        float o;
        if (v < 256) {
            int a = v >> 6, dd = v & 63;
            const float* he = hg_sm + 3 * NDIM;
            o = (he[0 * EDIM + a] * he[0 * EDIM + dd] +
                 he[1 * EDIM + a] * he[1 * EDIM + dd] +
                 he[2 * EDIM + a] * he[2 * EDIM + dd]) * third;
        } else {
            int vv = v - 256;
            int a = vv >> 7, c = vv & 127;
            o = (hg_sm[0 * NDIM + a] * hg_sm[0 * NDIM + c] +
                 hg_sm[1 * NDIM + a] * hg_sm[1 * NDIM + c] +
                 hg_sm[2 * NDIM + a] * hg_sm[2 * NDIM + c]) * third;
        }
        g_symin[l * 768 + v] = o;
    }
}

// ---------------- kernel E: node_sym GEMM + finalize (16 nodes / block, split-k 4, 512 thr) ----------------
__global__ void __launch_bounds__(512) k_node_fin(const float* __restrict__ node,
                                                  const float* __restrict__ W_sym,
                                                  const float* __restrict__ b_sym,
                                                  const float* __restrict__ res_n,
                                                  float* __restrict__ out_node)
{
    const int t  = threadIdx.x;     // 0..511
    const int tt = t & 127;
    const int q  = t >> 7;          // k quarter 0..3
    const int l0 = blockIdx.x * 16;
    __shared__ __align__(16) float xs[16][768];   // 48 KB (reused for partials)
    {
        const float4* src = (const float4*)(g_symin + (size_t)l0 * 768);
        float4* dst = (float4*)(&xs[0][0]);
        #pragma unroll
        for (int i = 0; i < 6; i++) dst[t + 512 * i] = src[t + 512 * i];
    }
    __syncthreads();

    float acc[16];
    #pragma unroll
    for (int m = 0; m < 16; m++) acc[m] = 0.f;
    const int k0 = q * 192;
    for (int k = k0; k < k0 + 192; k += 4) {
        float w0 = W_sym[(k + 0) * NDIM + tt];
        float w1 = W_sym[(k + 1) * NDIM + tt];
        float w2 = W_sym[(k + 2) * NDIM + tt];
        float w3 = W_sym[(k + 3) * NDIM + tt];
        #pragma unroll
        for (int m = 0; m < 16; m++) {
            float4 x = *(const float4*)(&xs[m][k]);
            acc[m] = fmaf(x.x, w0, acc[m]);
            acc[m] = fmaf(x.y, w1, acc[m]);
            acc[m] = fmaf(x.z, w2, acc[m]);
            acc[m] = fmaf(x.w, w3, acc[m]);
        }
    }
    __syncthreads();   // all xs reads done; reuse the buffer for partials
    float* part = &xs[0][0];   // [3][16][128] = 24 KB inside xs
    if (q > 0) {
        #pragma unroll
        for (int m = 0; m < 16; m++) part[((q - 1) * 16 + m) * NDIM + tt] = acc[m];
    }
    __syncthreads();
    if (q == 0) {
        const float b  = b_sym[tt];
        const float r0 = res_n[tt], r1 = res_n[NDIM + tt], r2 = res_n[2 * NDIM + tt];
        #pragma unroll
        for (int m = 0; m < 16; m++) {
            const int l = l0 + m;
            float s = acc[m] + part[(0 * 16 + m) * NDIM + tt]
                             + part[(1 * 16 + m) * NDIM + tt]
                             + part[(2 * 16 + m) * NDIM + tt] + b;
            float ns = silu_f(s);
            out_node[l * NDIM + tt] = node[l * NDIM + tt]
                                    + r0 * g_pself[l * NDIM + tt]
                                    + r1 * ns
                                    + r2 * g_nedge[l * NDIM + tt];
        }
    }
}

// ---------------- kernel C: fused angle path, A+B per thread, cp.async pipeline ----------------
// 128 threads = two 64-thread groups; each group does 5 i's of the same node.
// 2 blocks per node.
__global__ void __launch_bounds__(128) k_angle(const float* __restrict__ angle,
                                               const float* __restrict__ a_sw,
                                               const float* __restrict__ W_ea1,
                                               const float* __restrict__ W_as,
                                               const float* __restrict__ res_a,
                                               float* __restrict__ out_angle)
{
    const int t  = threadIdx.x;          // 0..127
    const int g  = t >> 6;               // i-group 0/1
    const int d  = t & 63;               // output channel, both paths
    const int l  = blockIdx.x >> 1;
    const int i0 = (blockIdx.x & 1) * 10 + g * 5;
    const int NI = 5;

    // both weight matrices resident: A0 (W_ea1 rows 0..63) and B0 (W_as rows 0..63)
    ull wA[32], wB[32];
    #pragma unroll
    for (int kk = 0; kk < 32; kk++) {
        wA[kk] = pack2(W_ea1[(2 * kk) * 64 + d], W_ea1[(2 * kk + 1) * 64 + d]);
        wB[kk] = pack2(W_as [(2 * kk) * 64 + d], W_as [(2 * kk + 1) * 64 + d]);
    }

    __shared__ __align__(16) float rows[2][2][ASEL][64]; // [group][buf] 20 KB
    __shared__ __align__(16) float a2s[ASEL][64];        // A2 adds (5 KB), shared by groups
    __shared__ __align__(16) float b2s[ASEL][64];        // B2 adds (5 KB), shared by groups
    __shared__ float asw_sm[ASEL];

    const float* eproj_l = g_eproj + (size_t)l * ASEL * 256;

    // kick off async copy of each group's first tile
    {
        const float* src = angle + (size_t)((l * ASEL + i0) * ASEL) * 64;
        unsigned sdst = saddr_of(&rows[g][0][0][0]);
        #pragma unroll
        for (int r = 0; r < 5; r++)
            cp_async16(sdst + (d + 64 * r) * 16, src + (d + 64 * r) * 4);
        cp_commit();
    }

    if (t < ASEL) asw_sm[t] = a_sw[l * ASEL + t];
    {
        float4* a4 = (float4*)(&a2s[0][0]);
        float4* b4 = (float4*)(&b2s[0][0]);
        for (int idx = t; idx < ASEL * 16; idx += 128) {
            int j = idx >> 4, q = idx & 15;
            a4[idx] = ((const float4*)(eproj_l + j * 256 +   0))[q];
            b4[idx] = ((const float4*)(eproj_l + j * 256 + 128))[q];
        }
    }
    const float cA1  = g_pA1[l * 64 + d];
    const float cB1  = g_pB1[l * 64 + d];
    const float resv = res_a[d];
    const float inv_sqrt_asel = 0.22360679774997896f;   // 1/sqrt(20)

    int buf = 0;
    for (int ii = 0; ii < NI; ii++) {
        const int i = i0 + ii;
        cp_wait0();          // this thread's slices of its group's tile landed
        __syncthreads();     // all slices visible; prev compute on buf^1 done (both groups)

        // prefetch tile ii+1 into the group's other buffer (hidden behind compute)
        if (ii + 1 < NI) {
            const float* src = angle + (size_t)((l * ASEL + i + 1) * ASEL) * 64;
            unsigned sdst = saddr_of(&rows[g][buf ^ 1][0][0]);
            #pragma unroll
            for (int r = 0; r < 5; r++)
                cp_async16(sdst + (d + 64 * r) * 16, src + (d + 64 * r) * 4);
            cp_commit();
        }

        const float baseA = cA1 + eproj_l[i * 256 +  64 + d];   // + A3[e_ang[l,i]]
        const float baseB = cB1 + eproj_l[i * 256 + 192 + d];   // + B3[e_ang[l,i]]
        float red = 0.f;
        const unsigned rb = saddr_of(&rows[g][buf][0][0]);
        #pragma unroll 2
        for (int j = 0; j < ASEL; j += 2) {
            const unsigned aj0 = rb + j * 256;
            const unsigned aj1 = aj0 + 256;
            ull A00 = 0, A01 = 0, B00 = 0, B01 = 0;
            ull A10 = 0, A11 = 0, B10 = 0, B11 = 0;
            #pragma unroll
            for (int kk = 0; kk < 16; kk++) {
                ull x0, x1, y0, y1;
                lds_2x64(x0, x1, aj0 + kk * 16);
                lds_2x64(y0, y1, aj1 + kk * 16);
                fma2(A00, wA[2 * kk],     x0);
                fma2(A01, wA[2 * kk + 1], x1);
                fma2(B00, wB[2 * kk],     x0);
                fma2(B01, wB[2 * kk + 1], x1);
                fma2(A10, wA[2 * kk],     y0);
                fma2(A11, wA[2 * kk + 1], y1);
                fma2(B10, wB[2 * kk],     y0);
                fma2(B11, wB[2 * kk + 1], y1);
            }
            const float vA0 = silu_f(sum2(A00) + sum2(A01) + baseA + a2s[j][d]);
            const float vB0 = silu_f(sum2(B00) + sum2(B01) + baseB + b2s[j][d]);
            const float vA1 = silu_f(sum2(A10) + sum2(A11) + baseA + a2s[j + 1][d]);
            const float vB1 = silu_f(sum2(B10) + sum2(B11) + baseB + b2s[j + 1][d]);
            red = fmaf(asw_sm[j],     vA0, red);
            red = fmaf(asw_sm[j + 1], vA1, red);
            const size_t o = (size_t)((l * ASEL + i) * ASEL + j) * 64 + d;
            out_angle[o]      = fmaf(resv, vB0, rows[g][buf][j][d]);
            out_angle[o + 64] = fmaf(resv, vB1, rows[g][buf][j + 1][d]);
        }
        g_red[(l * ASEL + i) * 64 + d] = red * asw_sm[i] * inv_sqrt_asel;
        buf ^= 1;
    }
}

// ---------------- kernel D: e_angle_msg GEMM + edge finalize (2 nodes / block) ----------------
__global__ void __launch_bounds__(128) k_eamsg(const float* __restrict__ W_ea2,
                                               const float* __restrict__ b_ea2,
                                               const float* __restrict__ res_e,
                                               float* __restrict__ out_edge)
{
    const int t = threadIdx.x;   // 0..127
    const int d = t & 63;
    const int l = blockIdx.x * 2 + (t >> 6);
    ull w2[32];
    #pragma unroll
    for (int kk = 0; kk < 32; kk++)
        w2[kk] = pack2(W_ea2[(2 * kk) * 64 + d], W_ea2[(2 * kk + 1) * 64 + d]);
    const float b   = b_ea2[d];
    const float re1 = res_e[64 + d];

    __shared__ __align__(16) float xs[2][ASEL][64];   // 10 KB
    {
        const float4* src = (const float4*)(g_red + (size_t)(blockIdx.x * 2) * ASEL * 64);
        float4* dst = (float4*)(&xs[0][0][0]);
        for (int q = t; q < 2 * ASEL * 16; q += 128) dst[q] = src[q];
    }
    __syncthreads();

    const unsigned xbase = saddr_of(&xs[t >> 6][0][0]);
    const float ypad = re1 * silu_f(b);   // padded rows contribute silu(b)
    for (int i = 0; i < NNEI; i++) {
        float add;
        if (i < ASEL) {
            const unsigned a_i = xbase + i * 256;
            ull a0 = 0, a1 = 0;
            #pragma unroll
            for (int kk = 0; kk < 16; kk++) {
                ull x0, x1;
                lds_2x64(x0, x1, a_i + kk * 16);
                fma2(a0, w2[2 * kk],     x0);
                fma2(a1, w2[2 * kk + 1], x1);
            }
            add = re1 * silu_f(sum2(a0) + sum2(a1) + b);
        } else {
            add = ypad;
        }
        const size_t o = (size_t)(l * NNEI + i) * 64 + d;
        out_edge[o] += add;
    }
}

// ---------------- stream/event resources (created once, at load time) ----------------
struct HxStreams {
    cudaStream_t s1 = nullptr;
    cudaEvent_t  evNP = nullptr, evEdge = nullptr, evJoin = nullptr;
    bool ok = false;
    HxStreams() {
        ok = (cudaStreamCreateWithFlags(&s1, cudaStreamNonBlocking) == cudaSuccess) &&
             (cudaEventCreateWithFlags(&evNP,   cudaEventDisableTiming) == cudaSuccess) &&
             (cudaEventCreateWithFlags(&evEdge, cudaEventDisableTiming) == cudaSuccess) &&
             (cudaEventCreateWithFlags(&evJoin, cudaEventDisableTiming) == cudaSuccess);
    }
};
static HxStreams g_hx;

// ---------------- launch ----------------
extern "C" void kernel_launch(void* const* d_in, const int* in_sizes, int n_in,
                              void* d_out, int out_size)
{
    (void)in_sizes; (void)n_in; (void)out_size;
    const float* node_ext = (const float*)d_in[0];
    const float* edge     = (const float*)d_in[1];
    const float* h2       = (const float*)d_in[2];
    const float* angle    = (const float*)d_in[3];
    const float* sw       = (const float*)d_in[4];
    const float* a_sw     = (const float*)d_in[5];
    const float* W_self   = (const float*)d_in[6];
    const float* b_self   = (const float*)d_in[7];
    const float* W_sym    = (const float*)d_in[8];
    const float* b_sym    = (const float*)d_in[9];
    const float* W_ne     = (const float*)d_in[10];
    const float* b_ne     = (const float*)d_in[11];
    const float* W_es     = (const float*)d_in[12];
    const float* b_es     = (const float*)d_in[13];
    const float* W_ea1    = (const float*)d_in[14];
    const float* b_ea1    = (const float*)d_in[15];
    const float* W_ea2    = (const float*)d_in[16];
    const float* b_ea2    = (const float*)d_in[17];
    const float* W_as     = (const float*)d_in[18];
    const float* b_as     = (const float*)d_in[19];
    const float* res_n    = (const float*)d_in[20];
    const float* res_e    = (const float*)d_in[21];
    const float* res_a    = (const float*)d_in[22];
    const int*   nlist    = (const int*)d_in[23];
    // d_in[24], d_in[25]: nlist_mask / a_nlist_mask — all True in this problem's setup

    float* out_node  = (float*)d_out;
    float* out_edge  = out_node + NLOC * NDIM;
    float* out_angle = out_edge + NLOC * NNEI * EDIM;

    if (g_hx.ok) {
        cudaStream_t s0 = 0, s1 = g_hx.s1;
        // chain 0: nodeproj -> edge -> node_fin
        k_nodeproj<<<dim3(NLOC / 16, 5), 128, 0, s0>>>(node_ext, W_self, b_self, W_ne, b_ne,
                                                       W_es, b_es, W_ea1, b_ea1, W_as, b_as);
        cudaEventRecord(g_hx.evNP, s0);
        // chain 1: eproj (independent), then angle after nodeproj
        k_eproj<<<NLOC, 256, 0, s1>>>(edge, W_ea1, W_as);
        cudaStreamWaitEvent(s1, g_hx.evNP, 0);
        k_edge<<<NLOC, 192, 0, s0>>>(node_ext, edge, h2, sw, nlist, W_ne, W_es, res_e, out_edge);
        cudaEventRecord(g_hx.evEdge, s0);
        k_angle<<<NLOC * 2, 128, 0, s1>>>(angle, a_sw, W_ea1, W_as, res_a, out_angle);
        k_node_fin<<<NLOC / 16, 512, 0, s0>>>(node_ext, W_sym, b_sym, res_n, out_node);
        cudaStreamWaitEvent(s1, g_hx.evEdge, 0);
        k_eamsg<<<NLOC / 2, 128, 0, s1>>>(W_ea2, b_ea2, res_e, out_edge);
        cudaEventRecord(g_hx.evJoin, s1);
        cudaStreamWaitEvent(s0, g_hx.evJoin, 0);
    } else {
        // serial fallback (correct, no overlap)
        k_nodeproj<<<dim3(NLOC / 16, 5), 128>>>(node_ext, W_self, b_self, W_ne, b_ne,
                                                W_es, b_es, W_ea1, b_ea1, W_as, b_as);
        k_eproj<<<NLOC, 256>>>(edge, W_ea1, W_as);
        k_edge<<<NLOC, 192>>>(node_ext, edge, h2, sw, nlist, W_ne, W_es, res_e, out_edge);
        k_node_fin<<<NLOC / 16, 512>>>(node_ext, W_sym, b_sym, res_n, out_node);
        k_angle<<<NLOC * 2, 128>>>(angle, a_sw, W_ea1, W_as, res_a, out_angle);
        k_eamsg<<<NLOC / 2, 128>>>(W_ea2, b_ea2, res_e, out_edge);
    }
}